// round 13
// baseline (speedup 1.0000x reference)
#include <cuda_runtime.h>
#include <cuda_bf16.h>

#define NBATCH 256
#define LSEQ   4096
#define KER    15
#define LOUT   (LSEQ - KER + 1)   // 4082
#define DL     64
#define DC     128
#define NIV    (KER * 4)          // 60
#define HALF   2048               // positions per main block

// ---------------- device scratch (rewritten every launch) ----------------
__device__ __align__(16) float g_U[NIV * DC];      // isq * Wc * Wk^T
__device__ __align__(16) float g_V[NIV * DC];      // (Wc * Wq^T) / LOUT
__device__ __align__(16) float g_WvWc[DC * NIV];   // Wv * Wc^T
__device__ __align__(16) float g_w[DC];            // bq + Wq*conv_b
__device__ __align__(16) float g_ob[DC];           // bv + Wv*conv_b
__device__ unsigned long long g_fin[NBATCH][48];   // per-row fixed-point partials

#define SCALE_F  1099511627776.0f          // 2^40
#define INV_SCALE (1.0f / 1099511627776.0f)

#define FOR15(F) F(0) F(1) F(2) F(3) F(4) F(5) F(6) F(7) F(8) F(9) F(10) F(11) F(12) F(13) F(14)

// ================= setup: 61 blocks x 128 thr =================
// block iv<60: Wc row iv -> U row, V row, WvWc column (no cross-block deps!)
// block 60: w, ob, zero g_fin
__global__ void __launch_bounds__(128)
k_setup(const float* __restrict__ emb,   const float* __restrict__ conv_w,
        const float* __restrict__ conv_b,
        const float* __restrict__ Wq,    const float* __restrict__ bq,
        const float* __restrict__ Wk,    const float* __restrict__ Wv,
        const float* __restrict__ bv) {
    const int tid = threadIdx.x, iv = blockIdx.x;
    if (iv == 60) {
        if (tid < DC) {
            float sw_ = bq[tid], so = bv[tid];
            for (int e = 0; e < DC; e++) {
                float cb = conv_b[e];
                sw_ += Wq[tid * DC + e] * cb;
                so  += Wv[tid * DC + e] * cb;
            }
            g_w[tid] = sw_;
            g_ob[tid] = so;
        }
        for (int idx = tid; idx < NBATCH * 48; idx += 128)
            ((unsigned long long*)g_fin)[idx] = 0ull;
        return;
    }
    __shared__ float wcrow[DC];
    const int i = iv >> 2, v = iv & 3;
    // Wc[iv][c] = sum_d emb[v][d] * conv_w[c][d][i]
    {
        float s = 0.f;
        const float* cw = conv_w + (size_t)tid * (DL * KER) + i;
        const float* em = emb + v * DL;
#pragma unroll 16
        for (int d = 0; d < DL; d++) s += em[d] * cw[d * KER];
        wcrow[tid] = s;
    }
    __syncthreads();
    const float isq = 0.088388347648318447f;  // 1/sqrt(128)
    float su = 0.f, sv = 0.f, sw = 0.f;
#pragma unroll 8
    for (int d = 0; d < DC; d++) {
        float wc = wcrow[d];
        su += wc * Wk[tid * DC + d];
        sv += wc * Wq[tid * DC + d];
        sw += wc * Wv[tid * DC + d];
    }
    g_U[iv * DC + tid] = su * isq;
    g_V[iv * DC + tid] = sv * (1.0f / (float)LOUT);
    g_WvWc[tid * NIV + iv] = sw;
}

// ================= main: 512 blocks x 256 thr, half-row each =================
__global__ void __launch_bounds__(256, 3)
k_main(const int* __restrict__ tokens) {
    __shared__ float Tbl[3072];
    __shared__ float e_s[256 * 9];
    __shared__ unsigned int Xs[131], Ys[131];
    __shared__ float t_s[DC];
    __shared__ float S_s[NIV], fcnt_s[NIV];
    __shared__ float wacc[8][48];
    __shared__ int hist_s[4];
    __shared__ float bmax_s;

    const int tid = threadIdx.x, lane = tid & 31, warp = tid >> 5;
    const int n = blockIdx.x >> 1;         // row
    const int h = blockIdx.x & 1;          // half

    if (tid < 4) hist_s[tid] = 0;
    if (tid == 0) { Xs[128] = Xs[129] = Xs[130] = 0u;
                    Ys[128] = Ys[129] = Ys[130] = 0u; }
    __syncthreads();

    // ---- full-row tokens -> bitplanes + histogram ----
    {
        const int* trow = tokens + (size_t)n * LSEQ;
        int n0 = 0, n1 = 0, n2 = 0, n3 = 0;
#pragma unroll
        for (int m = 0; m < 16; m++) {
            int t = trow[m * 256 + warp * 32 + lane];
            unsigned b0 = __ballot_sync(0xffffffffu, t & 1);
            unsigned b1 = __ballot_sync(0xffffffffu, t & 2);
            if (lane == 0) {
                Xs[m * 8 + warp] = b0; Ys[m * 8 + warp] = b1;
                int c3 = __popc(b0 & b1);
                int c1 = __popc(b0) - c3;
                int c2 = __popc(b1) - c3;
                n3 += c3; n1 += c1; n2 += c2; n0 += 32 - c1 - c2 - c3;
            }
        }
        if (lane == 0) {
            atomicAdd(&hist_s[0], n0); atomicAdd(&hist_s[1], n1);
            atomicAdd(&hist_s[2], n2); atomicAdd(&hist_s[3], n3);
        }
    }
    __syncthreads();

#define TOK_AT(p) ((int)(((Xs[(p) >> 5] >> ((p) & 31)) & 1u) | (((Ys[(p) >> 5] >> ((p) & 31)) & 1u) << 1)))

    if (tid < NIV) {   // sliding-window counts (full row)
        int i = tid >> 2, v = tid & 3;
        int cnt = hist_s[v];
        for (int p = 0; p < i; p++) cnt -= (TOK_AT(p) == v);
        for (int p = i + LOUT; p < LSEQ; p++) cnt -= (TOK_AT(p) == v);
        fcnt_s[tid] = (float)cnt;
    }
    __syncthreads();

    // ---- t = w + V^T fcnt ; S = U t ----
    if (tid < DC) {
        float s = g_w[tid];
#pragma unroll 12
        for (int j = 0; j < NIV; j++) s += g_V[j * DC + tid] * fcnt_s[j];
        t_s[tid] = s;
    }
    __syncthreads();
    if (tid < NIV) {
        const float4* u4 = (const float4*)(g_U + tid * DC);
        float s = 0.f;
#pragma unroll 8
        for (int q = 0; q < DC / 4; q++) {
            float4 f = u4[q];
            int e = q * 4;
            s += f.x * t_s[e] + f.y * t_s[e + 1] + f.z * t_s[e + 2] + f.w * t_s[e + 3];
        }
        S_s[tid] = s;
    }
    __syncthreads();

    // ---- chunk tables + maxima (softmax shift bound) ----
    {
        float m0 = -1e30f, m1 = -1e30f, m2 = -1e30f;
#pragma unroll
        for (int q = 0; q < 12; q++) {
            int idx = tid + q * 256;
            int k = idx >> 10, u = idx & 1023;
            int xb = u & 31, yb = u >> 5;
            float s = 0.f;
#pragma unroll
            for (int j = 0; j < 5; j++) {
                int v = ((xb >> j) & 1) | (((yb >> j) & 1) << 1);
                s += S_s[(5 * k + j) * 4 + v];
            }
            Tbl[idx] = s;
            if (q < 4) m0 = fmaxf(m0, s);
            else if (q < 8) m1 = fmaxf(m1, s);
            else m2 = fmaxf(m2, s);
        }
#pragma unroll
        for (int o = 16; o > 0; o >>= 1) {
            m0 = fmaxf(m0, __shfl_xor_sync(0xffffffffu, m0, o));
            m1 = fmaxf(m1, __shfl_xor_sync(0xffffffffu, m1, o));
            m2 = fmaxf(m2, __shfl_xor_sync(0xffffffffu, m2, o));
        }
        if (lane == 0) { wacc[warp][0] = m0; wacc[warp][1] = m1; wacc[warp][2] = m2; }
        __syncthreads();
        if (tid == 0) {
            float a = wacc[0][0], b = wacc[0][1], c = wacc[0][2];
#pragma unroll
            for (int w = 1; w < 8; w++) {
                a = fmaxf(a, wacc[w][0]); b = fmaxf(b, wacc[w][1]); c = fmaxf(c, wacc[w][2]);
            }
            bmax_s = a + b + c;
        }
        __syncthreads();
    }
    const float bmax = bmax_s;

    // ---- this block's 8 consecutive positions per thread ----
    const int base = h * HALF + tid * 8;
    const int wi = base >> 5;
    const int sh0 = base & 31;
    const unsigned x0 = Xs[wi], x1 = Xs[wi + 1];
    const unsigned y0 = Ys[wi], y1 = Ys[wi + 1];
    const int ebase = tid * 9;

#define RED_ONE(var, slot) { \
        float v_ = (var); \
        v_ += __shfl_xor_sync(0xffffffffu, v_, 16); \
        v_ += __shfl_xor_sync(0xffffffffu, v_, 8);  \
        v_ += __shfl_xor_sync(0xffffffffu, v_, 4);  \
        v_ += __shfl_xor_sync(0xffffffffu, v_, 2);  \
        v_ += __shfl_xor_sync(0xffffffffu, v_, 1);  \
        if (lane == 0) wacc[warp][slot] = v_; }

    // ---- PASS 1: e (store to shared) + Ex[15] + Ey[15] ----
    {
#define DECL1(i) float ax##i = 0.f, ay##i = 0.f;
        FOR15(DECL1)
#undef DECL1
#pragma unroll 2
        for (int j = 0; j < 8; j++) {
            int sh = sh0 + j;
            unsigned bx = __funnelshift_r(x0, x1, sh);
            unsigned by = __funnelshift_r(y0, y1, sh);
            int u0 = (bx & 31) | ((by & 31) << 5);
            int u1 = ((bx >> 5) & 31) | (((by >> 5) & 31) << 5);
            int u2 = ((bx >> 10) & 31) | (((by >> 10) & 31) << 5);
            float s = Tbl[u0] + Tbl[1024 + u1] + Tbl[2048 + u2];
            float ev = __expf(s - bmax);
            ev = (base + j < LOUT) ? ev : 0.f;
            e_s[ebase + j] = ev;
#define ADD1(i) ax##i += (bx & (1u << i)) ? ev : 0.f; \
                ay##i += (by & (1u << i)) ? ev : 0.f;
            FOR15(ADD1)
#undef ADD1
        }
#define RED1(i) RED_ONE(ax##i, i) RED_ONE(ay##i, 15 + i)
        FOR15(RED1)
#undef RED1
    }

    // ---- PASS 2: Exy[15] + E (e from shared) ----
    {
#define DECL2(i) float az##i = 0.f;
        FOR15(DECL2)
#undef DECL2
        float accE = 0.f;
#pragma unroll 2
        for (int j = 0; j < 8; j++) {
            int sh = sh0 + j;
            unsigned bxy = __funnelshift_r(x0, x1, sh) & __funnelshift_r(y0, y1, sh);
            float ev = e_s[ebase + j];
            accE += ev;
#define ADD2(i) az##i += (bxy & (1u << i)) ? ev : 0.f;
            FOR15(ADD2)
#undef ADD2
        }
#define RED2(i) RED_ONE(az##i, 30 + i)
        FOR15(RED2)
#undef RED2
        RED_ONE(accE, 45)
    }
#undef RED_ONE
    __syncthreads();

    // ---- block partials -> global u64 fixed-point (deterministic) ----
    if (tid < 46) {
        float s = 0.f;
#pragma unroll
        for (int w = 0; w < 8; w++) s += wacc[w][tid];
        atomicAdd(&g_fin[n][tid], (unsigned long long)(s * SCALE_F + 0.5f));
    }
}

// ================= final: 256 blocks x 128 thr =================
__global__ void __launch_bounds__(128)
k_final(float* __restrict__ out) {
    __shared__ float fin[46];
    __shared__ float A_s[NIV];
    const int tid = threadIdx.x, n = blockIdx.x;

    if (tid < 46) fin[tid] = (float)g_fin[n][tid] * INV_SCALE;
    __syncthreads();
    if (tid < NIV) {
        int i = tid >> 2, v = tid & 3;
        float E = fin[45], Ex = fin[i], Ey = fin[15 + i], Exy = fin[30 + i];
        A_s[tid] = (v == 3) ? Exy
                 : (v == 1) ? (Ex - Exy)
                 : (v == 2) ? (Ey - Exy)
                 : (E - Ex - Ey + Exy);
    }
    __syncthreads();
    if (tid < DC) {
        const float4* w4 = (const float4*)(g_WvWc + tid * NIV);
        float s = 0.f;
#pragma unroll
        for (int q = 0; q < NIV / 4; q++) {
            float4 f = w4[q];
            int j = q * 4;
            s += f.x * A_s[j] + f.y * A_s[j + 1] + f.z * A_s[j + 2] + f.w * A_s[j + 3];
        }
        out[(size_t)n * DC + tid] = g_ob[tid] + s / fin[45];
    }
}

// ---------------- launch ----------------
// Inputs: tokens, emb, conv_w, conv_b, Wq, bq, Wk, bk, Wv, bv  (bk drops out of softmax)
extern "C" void kernel_launch(void* const* d_in, const int* in_sizes, int n_in,
                              void* d_out, int out_size) {
    const int*   tokens = (const int*)  d_in[0];
    const float* emb    = (const float*)d_in[1];
    const float* conv_w = (const float*)d_in[2];
    const float* conv_b = (const float*)d_in[3];
    const float* Wq     = (const float*)d_in[4];
    const float* bq     = (const float*)d_in[5];
    const float* Wk     = (const float*)d_in[6];
    const float* Wv     = (const float*)d_in[8];
    const float* bv     = (const float*)d_in[9];
    float*       out    = (float*)d_out;

    k_setup<<<61, 128>>>(emb, conv_w, conv_b, Wq, bq, Wk, Wv, bv);
    k_main <<<2 * NBATCH, 256>>>(tokens);
    k_final<<<NBATCH, 128>>>(out);
}

// round 14
// speedup vs baseline: 1.6412x; 1.6412x over previous
#include <cuda_runtime.h>
#include <cuda_bf16.h>

#define NBATCH 256
#define NBLK   512                // 2 blocks per row
#define LSEQ   4096
#define KER    15
#define LOUT   (LSEQ - KER + 1)   // 4082
#define DL     64
#define DC     128
#define NIV    (KER * 4)          // 60
#define NTHR   256
#define HALF   2048

#define SCALE_F   17592186044416.0f          // 2^44
#define INV_SCALE (1.0f / 17592186044416.0f)

// ---------------- device scratch (rewritten every launch) ----------------
__device__ __align__(16) float g_U[NIV * DC];      // isq * Wc * Wk^T
__device__ __align__(16) float g_V[NIV * DC];      // (Wc * Wq^T) / LOUT
__device__ __align__(16) float g_WvWc[DC * NIV];   // Wv * Wc^T
__device__ __align__(16) float g_w[DC];            // bq + Wq*conv_b
__device__ __align__(16) float g_ob[DC];           // bv + Wv*conv_b
__device__ __align__(16) float g_Wc[NIV * DC];     // Wc[iv][c]
__device__ unsigned long long g_fin[NBATCH][48];   // per-row fixed-point partials
__device__ unsigned g_cnt[NBATCH];                 // per-row arrival counters

// ---------------- software grid barrier (sense-reversing) ----------------
__device__ unsigned g_barc = 0;
__device__ volatile unsigned g_sense = 0;

__device__ __forceinline__ void grid_barrier(int tid) {
    __syncthreads();
    if (tid == 0) {
        unsigned s = g_sense;
        __threadfence();
        unsigned old = atomicAdd(&g_barc, 1u);
        if (old == NBLK - 1) {
            g_barc = 0;
            __threadfence();
            g_sense = s ^ 1u;
        } else {
            while (g_sense == s) { }
        }
        __threadfence();
    }
    __syncthreads();
}

#define FOR15(F) F(0) F(1) F(2) F(3) F(4) F(5) F(6) F(7) F(8) F(9) F(10) F(11) F(12) F(13) F(14)

// 512 blocks x 256 threads, <=64 regs, ~25KB smem => 4 blocks/SM => 592 slots >= 512.
__global__ void __launch_bounds__(NTHR, 4)
seq_all(const int*   __restrict__ tokens,
        const float* __restrict__ emb,   const float* __restrict__ conv_w,
        const float* __restrict__ conv_b,
        const float* __restrict__ Wq,    const float* __restrict__ bq,
        const float* __restrict__ Wk,    const float* __restrict__ Wv,
        const float* __restrict__ bv,    float* __restrict__ out) {
    __shared__ float Tbl[3072];                 // chunk tables; aliased setup scratch
    __shared__ float e_s[NTHR * 9];             // padded exp cache
    __shared__ unsigned int Xs[131], Ys[131];
    __shared__ float t_s[DC];
    __shared__ float S_s[NIV], fcnt_s[NIV];
    __shared__ float wacc[8][48];
    __shared__ float fin[46];
    __shared__ float A_s[NIV];
    __shared__ int hist_s[4];
    __shared__ float bmax_s;
    __shared__ int last_s;

    const int tid = threadIdx.x, lane = tid & 31, warp = tid >> 5;
    const int bid = blockIdx.x;
    const int n = bid >> 1, h = bid & 1;
    float* scratch = Tbl;

    if (tid < 4) hist_s[tid] = 0;
    if (tid == 0) { Xs[128] = Xs[129] = Xs[130] = 0u;
                    Ys[128] = Ys[129] = Ys[130] = 0u; }
    __syncthreads();

    // ======== prologue: full-row tokens -> bitplanes + histogram ========
    {
        const int* trow = tokens + (size_t)n * LSEQ;
        int n0 = 0, n1 = 0, n2 = 0, n3 = 0;
#pragma unroll
        for (int m = 0; m < 16; m++) {
            int t = trow[m * NTHR + warp * 32 + lane];
            unsigned b0 = __ballot_sync(0xffffffffu, t & 1);
            unsigned b1 = __ballot_sync(0xffffffffu, t & 2);
            if (lane == 0) {
                Xs[m * 8 + warp] = b0; Ys[m * 8 + warp] = b1;
                int c3 = __popc(b0 & b1);
                int c1 = __popc(b0) - c3;
                int c2 = __popc(b1) - c3;
                n3 += c3; n1 += c1; n2 += c2; n0 += 32 - c1 - c2 - c3;
            }
        }
        if (lane == 0) {
            atomicAdd(&hist_s[0], n0); atomicAdd(&hist_s[1], n1);
            atomicAdd(&hist_s[2], n2); atomicAdd(&hist_s[3], n3);
        }
    }
    __syncthreads();

#define TOK_AT(p) ((int)(((Xs[(p) >> 5] >> ((p) & 31)) & 1u) | (((Ys[(p) >> 5] >> ((p) & 31)) & 1u) << 1)))

    if (tid < NIV) {   // sliding-window counts (full row)
        int i = tid >> 2, v = tid & 3;
        int cnt = hist_s[v];
        for (int p = 0; p < i; p++) cnt -= (TOK_AT(p) == v);
        for (int p = i + LOUT; p < LSEQ; p++) cnt -= (TOK_AT(p) == v);
        fcnt_s[tid] = (float)cnt;
    }

    // ======== setup phase 1 (blocks 0..127): Wc column c=bid; zero g_fin/g_cnt ====
    if (bid < DC) {
        float* cw   = scratch;          // 960 floats, coalesced
        float* embS = scratch + 960;    // 256
        for (int idx = tid; idx < DL * KER; idx += NTHR) cw[idx] = conv_w[bid * (DL * KER) + idx];
        for (int idx = tid; idx < 4 * DL;  idx += NTHR) embS[idx] = emb[idx];
        // zero 2 rows of g_fin + g_cnt per block
        if (tid < 48) g_fin[2 * bid][tid] = 0ull;
        else if (tid < 96) g_fin[2 * bid + 1][tid - 48] = 0ull;
        else if (tid == 96) { g_cnt[2 * bid] = 0u; g_cnt[2 * bid + 1] = 0u; }
        __syncthreads();
        if (tid < NIV) {
            int i = tid >> 2, v = tid & 3;
            float s = 0.f;
#pragma unroll 16
            for (int d = 0; d < DL; d++) s += embS[v * DL + d] * cw[d * KER + i];
            g_Wc[tid * DC + bid] = s;
        }
    }

    grid_barrier(tid);   // g_Wc + zeroing complete

    // ======== setup phase 2 (blocks 0..127): U, V, WvWc, w, ob ========
    if (bid < DC) {
        float* wkS = scratch;          float* wqS = scratch + DC;
        float* wvS = scratch + 2 * DC; float* cbS = scratch + 3 * DC;
        for (int idx = tid; idx < DC; idx += NTHR) {
            wkS[idx] = Wk[bid * DC + idx];
            wqS[idx] = Wq[bid * DC + idx];
            wvS[idx] = Wv[bid * DC + idx];
            cbS[idx] = conv_b[idx];
        }
        __syncthreads();
        const float isq = 0.088388347648318447f;  // 1/sqrt(128)
        if (tid < NIV) {
            const float4* wc4 = (const float4*)(g_Wc + tid * DC);
            float su = 0.f, sv = 0.f, sw = 0.f;
#pragma unroll 8
            for (int q = 0; q < DC / 4; q++) {
                float4 f = wc4[q];
                int d = q * 4;
                su += f.x * wkS[d] + f.y * wkS[d + 1] + f.z * wkS[d + 2] + f.w * wkS[d + 3];
                sv += f.x * wqS[d] + f.y * wqS[d + 1] + f.z * wqS[d + 2] + f.w * wqS[d + 3];
                sw += f.x * wvS[d] + f.y * wvS[d + 1] + f.z * wvS[d + 2] + f.w * wvS[d + 3];
            }
            g_U[tid * DC + bid] = su * isq;
            g_V[tid * DC + bid] = sv * (1.0f / (float)LOUT);
            g_WvWc[bid * NIV + tid] = sw;
        } else if (tid == 60) {
            float s = bq[bid];
#pragma unroll 8
            for (int e = 0; e < DC; e++) s += wqS[e] * cbS[e];
            g_w[bid] = s;
        } else if (tid == 61) {
            float s = bv[bid];
#pragma unroll 8
            for (int e = 0; e < DC; e++) s += wvS[e] * cbS[e];
            g_ob[bid] = s;
        }
    }

    grid_barrier(tid);   // setup complete

    // ======== per-batch score table: t = w + V'^T fcnt ; S = U' t ========
    if (tid < DC) {
        float s = g_w[tid];
#pragma unroll 12
        for (int j = 0; j < NIV; j++) s += g_V[j * DC + tid] * fcnt_s[j];
        t_s[tid] = s;
    }
    __syncthreads();
    if (tid < NIV) {
        const float4* u4 = (const float4*)(g_U + tid * DC);
        float s = 0.f;
#pragma unroll 8
        for (int q = 0; q < DC / 4; q++) {
            float4 f = u4[q];
            int e = q * 4;
            s += f.x * t_s[e] + f.y * t_s[e + 1] + f.z * t_s[e + 2] + f.w * t_s[e + 3];
        }
        S_s[tid] = s;
    }
    __syncthreads();

    // ======== chunk tables + per-chunk maxima (softmax shift bound) ========
    {
        float m0 = -1e30f, m1 = -1e30f, m2 = -1e30f;
#pragma unroll
        for (int q = 0; q < 12; q++) {
            int idx = tid + q * NTHR;
            int k = idx >> 10, u = idx & 1023;
            int xb = u & 31, yb = u >> 5;
            float s = 0.f;
#pragma unroll
            for (int j = 0; j < 5; j++) {
                int v = ((xb >> j) & 1) | (((yb >> j) & 1) << 1);
                s += S_s[(5 * k + j) * 4 + v];
            }
            Tbl[idx] = s;
            if (q < 4) m0 = fmaxf(m0, s);
            else if (q < 8) m1 = fmaxf(m1, s);
            else m2 = fmaxf(m2, s);
        }
#pragma unroll
        for (int o = 16; o > 0; o >>= 1) {
            m0 = fmaxf(m0, __shfl_xor_sync(0xffffffffu, m0, o));
            m1 = fmaxf(m1, __shfl_xor_sync(0xffffffffu, m1, o));
            m2 = fmaxf(m2, __shfl_xor_sync(0xffffffffu, m2, o));
        }
        if (lane == 0) { wacc[warp][0] = m0; wacc[warp][1] = m1; wacc[warp][2] = m2; }
        __syncthreads();
        if (tid == 0) {
            float a = wacc[0][0], b = wacc[0][1], c = wacc[0][2];
#pragma unroll
            for (int w = 1; w < 8; w++) {
                a = fmaxf(a, wacc[w][0]); b = fmaxf(b, wacc[w][1]); c = fmaxf(c, wacc[w][2]);
            }
            bmax_s = a + b + c;
        }
        __syncthreads();
    }
    const float bmax = bmax_s;

    // ======== this half-block's 8 consecutive positions per thread ========
    const int base = h * HALF + tid * 8;
    const int wi = base >> 5;
    const int sh0 = base & 31;
    const unsigned x0 = Xs[wi], x1 = Xs[wi + 1];
    const unsigned y0 = Ys[wi], y1 = Ys[wi + 1];
    const int ebase = tid * 9;

#define RED_ONE(var, slot) { \
        float v_ = (var); \
        v_ += __shfl_xor_sync(0xffffffffu, v_, 16); \
        v_ += __shfl_xor_sync(0xffffffffu, v_, 8);  \
        v_ += __shfl_xor_sync(0xffffffffu, v_, 4);  \
        v_ += __shfl_xor_sync(0xffffffffu, v_, 2);  \
        v_ += __shfl_xor_sync(0xffffffffu, v_, 1);  \
        if (lane == 0) wacc[warp][slot] = v_; }

    // ---- PASS A: e -> shared, accumulate E + Ex[15] ----
    {
        float accE = 0.f;
#define DECLA(i) float ax##i = 0.f;
        FOR15(DECLA)
#undef DECLA
#pragma unroll 2
        for (int j = 0; j < 8; j++) {
            int sh = sh0 + j;
            unsigned bx = __funnelshift_r(x0, x1, sh);
            unsigned by = __funnelshift_r(y0, y1, sh);
            int u0 = (bx & 31) | ((by & 31) << 5);
            int u1 = ((bx >> 5) & 31) | (((by >> 5) & 31) << 5);
            int u2 = ((bx >> 10) & 31) | (((by >> 10) & 31) << 5);
            float s = Tbl[u0] + Tbl[1024 + u1] + Tbl[2048 + u2];
            float ev = __expf(s - bmax);
            ev = (base + j < LOUT) ? ev : 0.f;
            e_s[ebase + j] = ev;
            accE += ev;
#define ADDA(i) ax##i += (bx & (1u << i)) ? ev : 0.f;
            FOR15(ADDA)
#undef ADDA
        }
#define REDA(i) RED_ONE(ax##i, i)
        FOR15(REDA)
#undef REDA
        RED_ONE(accE, 45)
    }

    // ---- PASS B: Ey[15] ----
    {
#define DECLB(i) float ay##i = 0.f;
        FOR15(DECLB)
#undef DECLB
#pragma unroll 2
        for (int j = 0; j < 8; j++) {
            unsigned by = __funnelshift_r(y0, y1, sh0 + j);
            float ev = e_s[ebase + j];
#define ADDB(i) ay##i += (by & (1u << i)) ? ev : 0.f;
            FOR15(ADDB)
#undef ADDB
        }
#define REDB(i) RED_ONE(ay##i, 15 + i)
        FOR15(REDB)
#undef REDB
    }

    // ---- PASS C: Exy[15] ----
    {
#define DECLC(i) float az##i = 0.f;
        FOR15(DECLC)
#undef DECLC
#pragma unroll 2
        for (int j = 0; j < 8; j++) {
            int sh = sh0 + j;
            unsigned bxy = __funnelshift_r(x0, x1, sh) & __funnelshift_r(y0, y1, sh);
            float ev = e_s[ebase + j];
#define ADDC(i) az##i += (bxy & (1u << i)) ? ev : 0.f;
            FOR15(ADDC)
#undef ADDC
        }
#define REDC(i) RED_ONE(az##i, 30 + i)
        FOR15(REDC)
#undef REDC
    }
#undef RED_ONE
    __syncthreads();

    // ---- half-block partials -> global u64 fixed-point (deterministic) ----
    if (tid < 46) {
        float s = 0.f;
#pragma unroll
        for (int w = 0; w < 8; w++) s += wacc[w][tid];
        atomicAdd(&g_fin[n][tid], (unsigned long long)(s * SCALE_F + 0.5f));
    }
    __syncthreads();

    // ---- last-arriving half finalizes the row ----
    if (tid == 0) {
        __threadfence();
        last_s = (atomicAdd(&g_cnt[n], 1u) == 1u) ? 1 : 0;
    }
    __syncthreads();
    if (last_s) {
        __threadfence();
        if (tid < 46) fin[tid] = (float)atomicAdd(&g_fin[n][tid], 0ull) * INV_SCALE;
        __syncthreads();
        if (tid < NIV) {
            int i = tid >> 2, v = tid & 3;
            float E = fin[45], Ex = fin[i], Ey = fin[15 + i], Exy = fin[30 + i];
            A_s[tid] = (v == 3) ? Exy
                     : (v == 1) ? (Ex - Exy)
                     : (v == 2) ? (Ey - Exy)
                     : (E - Ex - Ey + Exy);
        }
        __syncthreads();
        if (tid < DC) {
            const float4* w4 = (const float4*)(g_WvWc + tid * NIV);
            float s = 0.f;
#pragma unroll
            for (int q = 0; q < NIV / 4; q++) {
                float4 f = w4[q];
                int j = q * 4;
                s += f.x * A_s[j] + f.y * A_s[j + 1] + f.z * A_s[j + 2] + f.w * A_s[j + 3];
            }
            out[(size_t)n * DC + tid] = g_ob[tid] + s / fin[45];
        }
    }
}

// ---------------- launch: ONE kernel ----------------
// Inputs: tokens, emb, conv_w, conv_b, Wq, bq, Wk, bk, Wv, bv  (bk drops out of softmax)
extern "C" void kernel_launch(void* const* d_in, const int* in_sizes, int n_in,
                              void* d_out, int out_size) {
    const int*   tokens = (const int*)  d_in[0];
    const float* emb    = (const float*)d_in[1];
    const float* conv_w = (const float*)d_in[2];
    const float* conv_b = (const float*)d_in[3];
    const float* Wq     = (const float*)d_in[4];
    const float* bq     = (const float*)d_in[5];
    const float* Wk     = (const float*)d_in[6];
    const float* Wv     = (const float*)d_in[8];
    const float* bv     = (const float*)d_in[9];
    float*       out    = (float*)d_out;

    seq_all<<<NBLK, NTHR>>>(tokens, emb, conv_w, conv_b, Wq, bq, Wk, Wv, bv, out);
}

// round 15
// speedup vs baseline: 2.1919x; 1.3355x over previous
#include <cuda_runtime.h>
#include <cuda_bf16.h>

#define NBATCH 256
#define LSEQ   4096
#define KER    15
#define LOUT   (LSEQ - KER + 1)   // 4082
#define DL     64
#define DC     128
#define NIV    (KER * 4)          // 60
#define NTHR   256

// ---------------- device scratch (rewritten every launch) ----------------
__device__ __align__(16) float g_Wc[NIV * DC];     // Wc[iv][c]
__device__ __align__(16) float g_U[NIV * DC];      // isq * Wc * Wk^T
__device__ __align__(16) float g_V[NIV * DC];      // (Wc * Wq^T) / LOUT
__device__ __align__(16) float g_WvWc[DC * NIV];   // Wv * Wc^T
__device__ __align__(16) float g_w[DC];            // bq + Wq*conv_b
__device__ __align__(16) float g_ob[DC];           // bv + Wv*conv_b

// ---------------- software grid barrier (sense-reversing) ----------------
__device__ unsigned g_barc = 0;
__device__ volatile unsigned g_sense = 0;

__device__ __forceinline__ void grid_barrier(int tid) {
    __syncthreads();
    if (tid == 0) {
        unsigned s = g_sense;
        __threadfence();
        unsigned old = atomicAdd(&g_barc, 1u);
        if (old == NBATCH - 1) {
            g_barc = 0;
            __threadfence();
            g_sense = s ^ 1u;
        } else {
            while (g_sense == s) { }
        }
        __threadfence();
    }
    __syncthreads();
}

#define FOR15(F) F(0) F(1) F(2) F(3) F(4) F(5) F(6) F(7) F(8) F(9) F(10) F(11) F(12) F(13) F(14)

// 256 blocks x 256 threads, ~82KB smem => 2 blocks/SM (proven at 81KB in R12) => barrier safe.
__global__ void __launch_bounds__(NTHR, 2)
seq_all(const int*   __restrict__ tokens,
        const float* __restrict__ emb,   const float* __restrict__ conv_w,
        const float* __restrict__ conv_b,
        const float* __restrict__ Wq,    const float* __restrict__ bq,
        const float* __restrict__ Wk,    const float* __restrict__ Wv,
        const float* __restrict__ bv,    float* __restrict__ out) {
    extern __shared__ float dynsh[];
    float* Tbl = dynsh;                 // [3072] chunk tables / setup scratch
    // LUT: entry k of thread tid at dynsh[3072 + k*256 + tid]  -> bank = tid%32 ALWAYS
    float* lutb = dynsh + 3072 + threadIdx.x;

    __shared__ unsigned int Xs[129], Ys[129];
    __shared__ float t_s[DC];
    __shared__ float S_s[NIV], fcnt_s[NIV], A_s[NIV];
    __shared__ float wacc[8][48];
    __shared__ float fin[46];           // [0..14]=Ex, [15..29]=Ey, [30..44]=Exy, [45]=E
    __shared__ int hist_s[4];
    __shared__ float bmax_s;

    const int tid = threadIdx.x, lane = tid & 31, warp = tid >> 5;
    const int bid = blockIdx.x;
    float* scratch = Tbl;

    if (tid < 4) hist_s[tid] = 0;
    if (tid == 0) { Xs[128] = 0u; Ys[128] = 0u; }
    __syncthreads();

    // ======== prologue: tokens -> bitplanes + histogram ========
    {
        const int* trow = tokens + (size_t)bid * LSEQ;
        int n0 = 0, n1 = 0, n2 = 0, n3 = 0;
#pragma unroll
        for (int m = 0; m < 16; m++) {
            int t = trow[m * NTHR + warp * 32 + lane];
            unsigned b0 = __ballot_sync(0xffffffffu, t & 1);
            unsigned b1 = __ballot_sync(0xffffffffu, t & 2);
            if (lane == 0) {
                Xs[m * 8 + warp] = b0; Ys[m * 8 + warp] = b1;
                int c3 = __popc(b0 & b1);
                int c1 = __popc(b0) - c3;
                int c2 = __popc(b1) - c3;
                n3 += c3; n1 += c1; n2 += c2; n0 += 32 - c1 - c2 - c3;
            }
        }
        if (lane == 0) {
            atomicAdd(&hist_s[0], n0); atomicAdd(&hist_s[1], n1);
            atomicAdd(&hist_s[2], n2); atomicAdd(&hist_s[3], n3);
        }
    }
    __syncthreads();

#define TOK_AT(p) ((int)(((Xs[(p) >> 5] >> ((p) & 31)) & 1u) | (((Ys[(p) >> 5] >> ((p) & 31)) & 1u) << 1)))

    if (tid < NIV) {   // sliding-window counts
        int i = tid >> 2, v = tid & 3;
        int cnt = hist_s[v];
        for (int p = 0; p < i; p++) cnt -= (TOK_AT(p) == v);
        for (int p = i + LOUT; p < LSEQ; p++) cnt -= (TOK_AT(p) == v);
        fcnt_s[tid] = (float)cnt;
    }

    // ======== setup phase 1 (blocks 0..127): Wc column c=bid ========
    if (bid < DC) {
        float* cw   = scratch;          // 960 floats (coalesced stage)
        float* embS = scratch + 960;    // 256
        for (int idx = tid; idx < DL * KER; idx += NTHR) cw[idx] = conv_w[bid * (DL * KER) + idx];
        for (int idx = tid; idx < 4 * DL;  idx += NTHR) embS[idx] = emb[idx];
        __syncthreads();
        if (tid < NIV) {
            int i = tid >> 2, v = tid & 3;
            float s = 0.f;
#pragma unroll 16
            for (int d = 0; d < DL; d++) s += embS[v * DL + d] * cw[d * KER + i];
            g_Wc[tid * DC + bid] = s;
        }
    }

    grid_barrier(tid);   // g_Wc complete

    // ======== setup phase 2 (blocks 0..127): U, V, WvWc, w, ob ========
    if (bid < DC) {
        float* wkS = scratch;          float* wqS = scratch + DC;
        float* wvS = scratch + 2 * DC; float* cbS = scratch + 3 * DC;
        for (int idx = tid; idx < DC; idx += NTHR) {
            wkS[idx] = Wk[bid * DC + idx];
            wqS[idx] = Wq[bid * DC + idx];
            wvS[idx] = Wv[bid * DC + idx];
            cbS[idx] = conv_b[idx];
        }
        __syncthreads();
        const float isq = 0.088388347648318447f;  // 1/sqrt(128)
        if (tid < NIV) {
            const float4* wc4 = (const float4*)(g_Wc + tid * DC);
            float su = 0.f, sv = 0.f, sw = 0.f;
#pragma unroll 8
            for (int q = 0; q < DC / 4; q++) {
                float4 f = wc4[q];
                int d = q * 4;
                su += f.x * wkS[d] + f.y * wkS[d + 1] + f.z * wkS[d + 2] + f.w * wkS[d + 3];
                sv += f.x * wqS[d] + f.y * wqS[d + 1] + f.z * wqS[d + 2] + f.w * wqS[d + 3];
                sw += f.x * wvS[d] + f.y * wvS[d + 1] + f.z * wvS[d + 2] + f.w * wvS[d + 3];
            }
            g_U[tid * DC + bid] = su * isq;
            g_V[tid * DC + bid] = sv * (1.0f / (float)LOUT);
            g_WvWc[bid * NIV + tid] = sw;
        } else if (tid == 60) {
            float s = bq[bid];
#pragma unroll 8
            for (int e = 0; e < DC; e++) s += wqS[e] * cbS[e];
            g_w[bid] = s;
        } else if (tid == 61) {
            float s = bv[bid];
#pragma unroll 8
            for (int e = 0; e < DC; e++) s += wvS[e] * cbS[e];
            g_ob[bid] = s;
        }
    }

    grid_barrier(tid);   // setup complete

    // ======== per-batch score table: t = w + V'^T fcnt ; S = U' t ========
    if (tid < DC) {
        float s = g_w[tid];
#pragma unroll 12
        for (int j = 0; j < NIV; j++) s += g_V[j * DC + tid] * fcnt_s[j];
        t_s[tid] = s;
    }
    __syncthreads();
    if (tid < NIV) {
        const float4* u4 = (const float4*)(g_U + tid * DC);
        float s = 0.f;
#pragma unroll 8
        for (int q = 0; q < DC / 4; q++) {
            float4 f = u4[q];
            int e = q * 4;
            s += f.x * t_s[e] + f.y * t_s[e + 1] + f.z * t_s[e + 2] + f.w * t_s[e + 3];
        }
        S_s[tid] = s;
    }
    __syncthreads();

    // ======== chunk tables + per-chunk maxima (softmax shift bound) ========
    {
        float m0 = -1e30f, m1 = -1e30f, m2 = -1e30f;
#pragma unroll
        for (int q = 0; q < 12; q++) {
            int idx = tid + q * NTHR;
            int k = idx >> 10, u = idx & 1023;
            int xb = u & 31, yb = u >> 5;
            float s = 0.f;
#pragma unroll
            for (int j = 0; j < 5; j++) {
                int v = ((xb >> j) & 1) | (((yb >> j) & 1) << 1);
                s += S_s[(5 * k + j) * 4 + v];
            }
            Tbl[idx] = s;
            if (q < 4) m0 = fmaxf(m0, s);
            else if (q < 8) m1 = fmaxf(m1, s);
            else m2 = fmaxf(m2, s);
        }
#pragma unroll
        for (int o = 16; o > 0; o >>= 1) {
            m0 = fmaxf(m0, __shfl_xor_sync(0xffffffffu, m0, o));
            m1 = fmaxf(m1, __shfl_xor_sync(0xffffffffu, m1, o));
            m2 = fmaxf(m2, __shfl_xor_sync(0xffffffffu, m2, o));
        }
        if (lane == 0) { wacc[warp][0] = m0; wacc[warp][1] = m1; wacc[warp][2] = m2; }
        __syncthreads();
        if (tid == 0) {
            float a = wacc[0][0], b = wacc[0][1], c = wacc[0][2];
#pragma unroll
            for (int w = 1; w < 8; w++) {
                a = fmaxf(a, wacc[w][0]); b = fmaxf(b, wacc[w][1]); c = fmaxf(c, wacc[w][2]);
            }
            bmax_s = a + b + c;
        }
        __syncthreads();
    }
    const float bmax = bmax_s;

    // ======== window words: 16 consecutive positions per thread ========
    const int base = tid * 16;
    const int wi = base >> 5;
    const int sh0 = base & 31;                 // 0 or 16 (max shift used: sh0+15 <= 31)
    const unsigned x0 = Xs[wi], x1 = Xs[wi + 1];
    const unsigned y0 = Ys[wi], y1 = Ys[wi + 1];

    // ======== PASS A: e + 4 bank-aligned subset-sum LUTs (Four Russians) ========
    float accE = 0.f;
#pragma unroll
    for (int g = 0; g < 4; g++) {
        float ev[4];
#pragma unroll
        for (int r = 0; r < 4; r++) {
            int j = g * 4 + r;
            int sh = sh0 + j;
            unsigned bx = __funnelshift_r(x0, x1, sh);
            unsigned by = __funnelshift_r(y0, y1, sh);
            int u0 = (bx & 31) | ((by & 31) << 5);
            int u1 = ((bx >> 5) & 31) | (((by >> 5) & 31) << 5);
            int u2 = ((bx >> 10) & 31) | (((by >> 10) & 31) << 5);
            float s = Tbl[u0] + Tbl[1024 + u1] + Tbl[2048 + u2];
            float e = __expf(s - bmax);
            ev[r] = (base + j < LOUT) ? e : 0.f;
        }
        float l3  = ev[1] + ev[0];
        float l5  = ev[2] + ev[0];
        float l6  = ev[2] + ev[1];
        float l7  = ev[2] + l3;
        float l9  = ev[3] + ev[0];
        float l10 = ev[3] + ev[1];
        float l11 = ev[3] + l3;
        float l12 = ev[3] + ev[2];
        float l13 = ev[3] + l5;
        float l14 = ev[3] + l6;
        float l15 = ev[3] + l7;
        float* L = lutb + (g * 16) * NTHR;     // bank-aligned: stride NTHR per entry
        L[0] = 0.f;          L[1 * NTHR] = ev[0]; L[2 * NTHR] = ev[1]; L[3 * NTHR] = l3;
        L[4 * NTHR] = ev[2]; L[5 * NTHR] = l5;   L[6 * NTHR] = l6;    L[7 * NTHR] = l7;
        L[8 * NTHR] = ev[3]; L[9 * NTHR] = l9;   L[10 * NTHR] = l10;  L[11 * NTHR] = l11;
        L[12 * NTHR] = l12;  L[13 * NTHR] = l13; L[14 * NTHR] = l14;  L[15 * NTHR] = l15;
        accE += l15;
    }

#define RED_ONE(var, slot) { \
        float v_ = (var); \
        v_ += __shfl_xor_sync(0xffffffffu, v_, 16); \
        v_ += __shfl_xor_sync(0xffffffffu, v_, 8);  \
        v_ += __shfl_xor_sync(0xffffffffu, v_, 4);  \
        v_ += __shfl_xor_sync(0xffffffffu, v_, 2);  \
        v_ += __shfl_xor_sync(0xffffffffu, v_, 1);  \
        if (lane == 0) wacc[warp][slot] = v_; }

    RED_ONE(accE, 45)

    // 4-nibble LUT gather for one 16-bit field (zero-conflict: bank = tid%32 always)
#define LOOKUP4(f) ( (lutb[((f) & 15u) * NTHR] + lutb[(16 + (((f) >> 4) & 15u)) * NTHR]) \
                   + (lutb[(32 + (((f) >> 8) & 15u)) * NTHR] + lutb[(48 + (((f) >> 12) & 15u)) * NTHR]) )

    // ---- PASS X: Ex[15] ----
    {
#define DECLX(i) float ax##i = 0.f;
        FOR15(DECLX)
#undef DECLX
#define TAPX(i) { unsigned fx = __funnelshift_r(x0, x1, sh0 + i); ax##i += LOOKUP4(fx); }
        FOR15(TAPX)
#undef TAPX
#define REDX(i) RED_ONE(ax##i, i)
        FOR15(REDX)
#undef REDX
    }

    // ---- PASS Y: Ey[15] ----
    {
#define DECLY(i) float ay##i = 0.f;
        FOR15(DECLY)
#undef DECLY
#define TAPY(i) { unsigned fy = __funnelshift_r(y0, y1, sh0 + i); ay##i += LOOKUP4(fy); }
        FOR15(TAPY)
#undef TAPY
#define REDY(i) RED_ONE(ay##i, 15 + i)
        FOR15(REDY)
#undef REDY
    }

    // ---- PASS Z: Exy[15] ----
    {
#define DECLZ(i) float az##i = 0.f;
        FOR15(DECLZ)
#undef DECLZ
#define TAPZ(i) { unsigned fz = __funnelshift_r(x0, x1, sh0 + i) & __funnelshift_r(y0, y1, sh0 + i); \
                  az##i += LOOKUP4(fz); }
        FOR15(TAPZ)
#undef TAPZ
#define REDZ(i) RED_ONE(az##i, 30 + i)
        FOR15(REDZ)
#undef REDZ
    }
#undef RED_ONE
    __syncthreads();

    if (tid < 46) {
        float s = 0.f;
#pragma unroll
        for (int w = 0; w < 8; w++) s += wacc[w][tid];
        fin[tid] = s;
    }
    __syncthreads();

    // ---- A[i][v] from (E, Ex, Ey, Exy) ----
    if (tid < NIV) {
        int i = tid >> 2, v = tid & 3;
        float E = fin[45], Ex = fin[i], Ey = fin[15 + i], Exy = fin[30 + i];
        A_s[tid] = (v == 3) ? Exy
                 : (v == 1) ? (Ex - Exy)
                 : (v == 2) ? (Ey - Exy)
                 : (E - Ex - Ey + Exy);
    }
    __syncthreads();

    // ---- out[c] = ob[c] + (WvWc*A)[c]/E ----
    if (tid < DC) {
        const float4* w4 = (const float4*)(g_WvWc + tid * NIV);
        float s = 0.f;
#pragma unroll
        for (int q = 0; q < NIV / 4; q++) {
            float4 f = w4[q];
            int j = q * 4;
            s += f.x * A_s[j] + f.y * A_s[j + 1] + f.z * A_s[j + 2] + f.w * A_s[j + 3];
        }
        out[(size_t)bid * DC + tid] = g_ob[tid] + s / fin[45];
    }
}

// ---------------- launch: ONE kernel, dynamic shared ----------------
// Inputs: tokens, emb, conv_w, conv_b, Wq, bq, Wk, bk, Wv, bv  (bk drops out of softmax)
extern "C" void kernel_launch(void* const* d_in, const int* in_sizes, int n_in,
                              void* d_out, int out_size) {
    const int*   tokens = (const int*)  d_in[0];
    const float* emb    = (const float*)d_in[1];
    const float* conv_w = (const float*)d_in[2];
    const float* conv_b = (const float*)d_in[3];
    const float* Wq     = (const float*)d_in[4];
    const float* bq     = (const float*)d_in[5];
    const float* Wk     = (const float*)d_in[6];
    const float* Wv     = (const float*)d_in[8];
    const float* bv     = (const float*)d_in[9];
    float*       out    = (float*)d_out;

    const size_t shbytes = (size_t)(3072 + 64 * NTHR) * sizeof(float);  // 76 KB
    cudaFuncSetAttribute(seq_all, cudaFuncAttributeMaxDynamicSharedMemorySize, (int)shbytes);
    seq_all<<<NBATCH, NTHR, shbytes>>>(tokens, emb, conv_w, conv_b, Wq, bq, Wk, Wv, bv, out);
}